// round 1
// baseline (speedup 1.0000x reference)
#include <cuda_runtime.h>
#include <math.h>

// Problem constants (GraphEmbedderGATNE): N=200000, R=4, D=128, U=32, A=16, E=131072, K=10
#define N_ENT 200000
#define R_ 4
#define D_ 128
#define U_ 32
#define A_ 16
#define E_ 131072
#define K_ 10
#define ES_TOTAL (2 * E_)          // 262144 edge-sides
#define WPB 16                      // warps per block
#define ES_PER_WARP 4
#define THREADS (WPB * 32)          // 512
#define ES_PER_BLOCK (WPB * ES_PER_WARP)  // 64
#define NBLOCKS (ES_TOTAL / ES_PER_BLOCK) // 4096 exactly

// Shared-memory layout (float offsets)
#define SM_M 0                            // M: [ (r*32+u)*128 + d ], 16384 floats
#define SM_W (SM_M + R_ * U_ * D_)        // W transposed: [r*512 + a*32 + u], 2048 floats
#define SM_w (SM_W + R_ * U_ * A_)        // w: [r*16 + a], 64 floats
#define SM_WARP0 (SM_w + R_ * A_)
// per-warp scratch:
#define Q_OFF 0                           // q: [b*128 + r*32 + u], 512 floats
#define UR_OFF 512                        // ur: [u*5 + r] (pad 5 -> conflict free), 160 floats
#define WR_OFF (UR_OFF + 160)             // Wr: [u*17 + a] (pad 17 -> conflict free), 544 floats
#define WARP_FLOATS (WR_OFF + 544)        // 1216 floats / warp
#define SMEM_FLOATS (SM_WARP0 + WPB * WARP_FLOATS)
#define SMEM_BYTES (SMEM_FLOATS * 4)      // 151808 bytes

// One mat-vec micro-step: consume component COMP of the 4 cached q-float4s
// against M row (ru4*4 + J); 16 FMAs (4 edge-sides x 4 d) per LDS.128 of M.
#define MSTEP(J, COMP) do {                                                   \
    float4 mv = M4s[(ru4 * 4 + (J)) * 32 + lane];                             \
    acc[0].x = fmaf(qv0.COMP, mv.x, acc[0].x);                                \
    acc[0].y = fmaf(qv0.COMP, mv.y, acc[0].y);                                \
    acc[0].z = fmaf(qv0.COMP, mv.z, acc[0].z);                                \
    acc[0].w = fmaf(qv0.COMP, mv.w, acc[0].w);                                \
    acc[1].x = fmaf(qv1.COMP, mv.x, acc[1].x);                                \
    acc[1].y = fmaf(qv1.COMP, mv.y, acc[1].y);                                \
    acc[1].z = fmaf(qv1.COMP, mv.z, acc[1].z);                                \
    acc[1].w = fmaf(qv1.COMP, mv.w, acc[1].w);                                \
    acc[2].x = fmaf(qv2.COMP, mv.x, acc[2].x);                                \
    acc[2].y = fmaf(qv2.COMP, mv.y, acc[2].y);                                \
    acc[2].z = fmaf(qv2.COMP, mv.z, acc[2].z);                                \
    acc[2].w = fmaf(qv2.COMP, mv.w, acc[2].w);                                \
    acc[3].x = fmaf(qv3.COMP, mv.x, acc[3].x);                                \
    acc[3].y = fmaf(qv3.COMP, mv.y, acc[3].y);                                \
    acc[3].z = fmaf(qv3.COMP, mv.z, acc[3].z);                                \
    acc[3].w = fmaf(qv3.COMP, mv.w, acc[3].w);                                \
} while (0)

__global__ void __launch_bounds__(THREADS, 1)
gatne_kernel(const int* __restrict__ edge_index,    // [2, E]
             const float* __restrict__ edge_attr,   // [E, R]
             const int* __restrict__ nidx,          // [2, E, K]
             const float* __restrict__ emb,         // [N, D]
             const float* __restrict__ utab,        // [N, R, U]
             const float* __restrict__ Wt,          // [R, U, A]
             const float* __restrict__ wv,          // [R, A]
             const float* __restrict__ Mt,          // [R, U, D]
             float* __restrict__ out)               // [2, E, D]
{
    extern __shared__ float smem[];
    const int tid = threadIdx.x;

    // --- cooperative loads of the shared weight tables ---
    {
        float4* d = (float4*)(smem + SM_M);
        const float4* s = (const float4*)Mt;
        for (int i = tid; i < (R_ * U_ * D_) / 4; i += THREADS) d[i] = s[i];
    }
    for (int i = tid; i < R_ * U_ * A_; i += THREADS) {
        int r = i >> 9, rem = i & 511, uu = rem >> 4, a = rem & 15;
        smem[SM_W + r * 512 + a * 32 + uu] = Wt[i];
    }
    if (tid < R_ * A_) smem[SM_w + tid] = wv[tid];
    __syncthreads();

    const int warp = tid >> 5, lane = tid & 31;
    float* q_s  = smem + SM_WARP0 + warp * WARP_FLOATS;
    float* ur_s = q_s + UR_OFF;
    float* wr_s = q_s + WR_OFF;
    const float* W_s = smem + SM_W;
    const float* w_s = smem + SM_w;

    const int es_base = (blockIdx.x * WPB + warp) * ES_PER_WARP;
    const int rg = lane >> 3;          // r-group for the t/score phase
    const int cg = lane & 7;
    const int a0 = 2 * cg, a1 = a0 + 1;

    // ================= Phase 1: per edge-side attention -> q =================
    #pragma unroll
    for (int b = 0; b < ES_PER_WARP; ++b) {
        const int es = es_base + b;
        const int e = es & (E_ - 1);
        const float4 ea = ((const float4*)edge_attr)[e];

        // mean over K neighbors of u rows: lane holds flat (r*32+u) = 4*lane..4*lane+3
        const int* nb = nidx + es * K_;
        float4 au = make_float4(0.f, 0.f, 0.f, 0.f);
        #pragma unroll
        for (int k = 0; k < K_; ++k) {
            int nbr = __ldg(nb + k);
            float4 t = ((const float4*)utab)[nbr * 32 + lane];
            au.x += t.x; au.y += t.y; au.z += t.z; au.w += t.w;
        }
        const float ik = 1.0f / (float)K_;
        au.x *= ik; au.y *= ik; au.z *= ik; au.w *= ik;

        // stash u_r to smem: layout [u*5 + r] (conflict-free)
        const int ub = 4 * cg;  // lane's flat index f = 4*lane+j -> r = lane>>3, u = 4*(lane&7)+j
        ur_s[(ub + 0) * 5 + rg] = au.x;
        ur_s[(ub + 1) * 5 + rg] = au.y;
        ur_s[(ub + 2) * 5 + rg] = au.z;
        ur_s[(ub + 3) * 5 + rg] = au.w;

        // W_r[u=lane][a] = sum_r ea[r] * W[r][u][a]  (W_s transposed [r][a][u])
        #pragma unroll
        for (int a = 0; a < A_; ++a) {
            float t = fmaf(ea.x, W_s[a * 32 + lane],
                      fmaf(ea.y, W_s[512 + a * 32 + lane],
                      fmaf(ea.z, W_s[1024 + a * 32 + lane],
                           ea.w * W_s[1536 + a * 32 + lane])));
            wr_s[lane * 17 + a] = t;
        }
        __syncwarp();

        // t[r=rg][a0], t[r=rg][a1] = sum_u u_r[r][u] * W_r[u][a]
        float t0 = 0.f, t1 = 0.f;
        #pragma unroll
        for (int uu = 0; uu < U_; ++uu) {
            float urv = ur_s[uu * 5 + rg];
            t0 = fmaf(urv, wr_s[uu * 17 + a0], t0);
            t1 = fmaf(urv, wr_s[uu * 17 + a1], t1);
        }
        // w_r[a] = ea . w[:, a]
        float wr0 = fmaf(ea.x, w_s[a0], fmaf(ea.y, w_s[16 + a0],
                    fmaf(ea.z, w_s[32 + a0], ea.w * w_s[48 + a0])));
        float wr1 = fmaf(ea.x, w_s[a1], fmaf(ea.y, w_s[16 + a1],
                    fmaf(ea.z, w_s[32 + a1], ea.w * w_s[48 + a1])));
        float sc = tanhf(t0) * wr0 + tanhf(t1) * wr1;

        // reduce scores within 8-lane r-group
        sc += __shfl_xor_sync(0xffffffffu, sc, 1);
        sc += __shfl_xor_sync(0xffffffffu, sc, 2);
        sc += __shfl_xor_sync(0xffffffffu, sc, 4);
        // softmax over the 4 r-groups
        float mx = sc;
        mx = fmaxf(mx, __shfl_xor_sync(0xffffffffu, mx, 8));
        mx = fmaxf(mx, __shfl_xor_sync(0xffffffffu, mx, 16));
        float ex = expf(sc - mx);
        float ssum = ex;
        ssum += __shfl_xor_sync(0xffffffffu, ssum, 8);
        ssum += __shfl_xor_sync(0xffffffffu, ssum, 16);
        float att = ex / ssum;  // attention for r = rg, replicated over its 8 lanes
        float av0 = __shfl_sync(0xffffffffu, att, 0);
        float av1 = __shfl_sync(0xffffffffu, att, 8);
        float av2 = __shfl_sync(0xffffffffu, att, 16);
        float av3 = __shfl_sync(0xffffffffu, att, 24);

        // v[u=lane] = sum_r att[r] * u_r[r][lane]
        float vv = fmaf(av0, ur_s[lane * 5 + 0],
                   fmaf(av1, ur_s[lane * 5 + 1],
                   fmaf(av2, ur_s[lane * 5 + 2],
                        av3 * ur_s[lane * 5 + 3])));

        // q[b][r*32+u] = ea[r] * v[u]
        q_s[b * 128 +      lane] = ea.x * vv;
        q_s[b * 128 + 32 + lane] = ea.y * vv;
        q_s[b * 128 + 64 + lane] = ea.z * vv;
        q_s[b * 128 + 96 + lane] = ea.w * vv;
        __syncwarp();
    }

    // ================= Phase 2: out = b + q @ M, batched over 4 edge-sides ===
    float4 acc[4];
    #pragma unroll
    for (int b = 0; b < 4; ++b) {
        int ent = __ldg(edge_index + es_base + b);
        acc[b] = ((const float4*)emb)[ent * 32 + lane];   // b gather, coalesced
    }
    const float4* M4s = (const float4*)(smem + SM_M);
    const float4* q4  = (const float4*)q_s;
    #pragma unroll 2
    for (int ru4 = 0; ru4 < 32; ++ru4) {
        float4 qv0 = q4[ru4];
        float4 qv1 = q4[32 + ru4];
        float4 qv2 = q4[64 + ru4];
        float4 qv3 = q4[96 + ru4];
        MSTEP(0, x); MSTEP(1, y); MSTEP(2, z); MSTEP(3, w);
    }

    // ================= L2-normalize rows and store =================
    #pragma unroll
    for (int b = 0; b < 4; ++b) {
        float ss = acc[b].x * acc[b].x + acc[b].y * acc[b].y
                 + acc[b].z * acc[b].z + acc[b].w * acc[b].w;
        ss += __shfl_xor_sync(0xffffffffu, ss, 1);
        ss += __shfl_xor_sync(0xffffffffu, ss, 2);
        ss += __shfl_xor_sync(0xffffffffu, ss, 4);
        ss += __shfl_xor_sync(0xffffffffu, ss, 8);
        ss += __shfl_xor_sync(0xffffffffu, ss, 16);
        float norm = sqrtf(ss);
        float inv = 1.0f / fmaxf(norm, 1e-12f);
        float4 o = acc[b];
        o.x *= inv; o.y *= inv; o.z *= inv; o.w *= inv;
        ((float4*)out)[(es_base + b) * 32 + lane] = o;
    }
}

extern "C" void kernel_launch(void* const* d_in, const int* in_sizes, int n_in,
                              void* d_out, int out_size)
{
    (void)in_sizes; (void)n_in; (void)out_size;
    const int*   edge_index = (const int*)d_in[0];
    const float* edge_attr  = (const float*)d_in[1];
    const int*   nidx       = (const int*)d_in[2];
    const float* emb        = (const float*)d_in[3];
    const float* utab       = (const float*)d_in[4];
    const float* Wt         = (const float*)d_in[5];
    const float* wv         = (const float*)d_in[6];
    const float* Mt         = (const float*)d_in[7];
    float* out = (float*)d_out;

    cudaFuncSetAttribute(gatne_kernel,
                         cudaFuncAttributeMaxDynamicSharedMemorySize, SMEM_BYTES);
    gatne_kernel<<<NBLOCKS, THREADS, SMEM_BYTES>>>(
        edge_index, edge_attr, nidx, emb, utab, Wt, wv, Mt, out);
}

// round 2
// speedup vs baseline: 1.6450x; 1.6450x over previous
#include <cuda_runtime.h>
#include <math.h>

// Problem constants (GraphEmbedderGATNE): N=200000, R=4, D=128, U=32, A=16, E=131072, K=10
#define N_ENT 200000
#define R_ 4
#define D_ 128
#define U_ 32
#define A_ 16
#define E_ 131072
#define K_ 10
#define ES_TOTAL (2 * E_)                 // 262144 edge-sides
#define WPB 32                            // warps per block
#define ES_PER_WARP 4
#define THREADS (WPB * 32)                // 1024
#define ES_PER_BLOCK (WPB * ES_PER_WARP)  // 128
#define NBLOCKS (ES_TOTAL / ES_PER_BLOCK) // 2048 exactly

// Shared-memory layout (float offsets)
#define SM_M 0                            // M: [(r*32+u)*128 + d], 16384 floats
#define SM_W (SM_M + R_ * U_ * D_)        // W transposed: [r*512 + a*32 + u], 2048 floats
#define SM_w (SM_W + R_ * U_ * A_)        // w: [r*16 + a], 64 floats
#define SM_WARP0 (SM_w + R_ * A_)         // 18496
// per-warp scratch:
#define Q_OFF 0                           // q: [b*128 + r*32 + u], 512 floats
#define UR_OFF 512                        // ur: [r*33 + u] (conflict-free), 132 floats
#define WR_OFF (UR_OFF + 132)             // Wr: [u*17 + a] (conflict-free), 544 floats
#define WARP_FLOATS (WR_OFF + 544)        // 1188 floats / warp
#define SMEM_FLOATS (SM_WARP0 + WPB * WARP_FLOATS)   // 56512
#define SMEM_BYTES (SMEM_FLOATS * 4)      // 226048 bytes (<= 232448 max dynamic)

__device__ __forceinline__ float tanh_fast(float x) {
    float y;
    asm("tanh.approx.f32 %0, %1;" : "=f"(y) : "f"(x));
    return y;
}

// One mat-vec micro-step: consume component COMP of the 4 cached q-float4s
// against M row (ru4*4 + J); 16 FMAs (4 edge-sides x 4 d) per LDS.128 of M.
#define MSTEP(J, COMP) do {                                                   \
    float4 mv = M4s[(ru4 * 4 + (J)) * 32 + lane];                             \
    acc[0].x = fmaf(qv0.COMP, mv.x, acc[0].x);                                \
    acc[0].y = fmaf(qv0.COMP, mv.y, acc[0].y);                                \
    acc[0].z = fmaf(qv0.COMP, mv.z, acc[0].z);                                \
    acc[0].w = fmaf(qv0.COMP, mv.w, acc[0].w);                                \
    acc[1].x = fmaf(qv1.COMP, mv.x, acc[1].x);                                \
    acc[1].y = fmaf(qv1.COMP, mv.y, acc[1].y);                                \
    acc[1].z = fmaf(qv1.COMP, mv.z, acc[1].z);                                \
    acc[1].w = fmaf(qv1.COMP, mv.w, acc[1].w);                                \
    acc[2].x = fmaf(qv2.COMP, mv.x, acc[2].x);                                \
    acc[2].y = fmaf(qv2.COMP, mv.y, acc[2].y);                                \
    acc[2].z = fmaf(qv2.COMP, mv.z, acc[2].z);                                \
    acc[2].w = fmaf(qv2.COMP, mv.w, acc[2].w);                                \
    acc[3].x = fmaf(qv3.COMP, mv.x, acc[3].x);                                \
    acc[3].y = fmaf(qv3.COMP, mv.y, acc[3].y);                                \
    acc[3].z = fmaf(qv3.COMP, mv.z, acc[3].z);                                \
    acc[3].w = fmaf(qv3.COMP, mv.w, acc[3].w);                                \
} while (0)

__global__ void __launch_bounds__(THREADS, 1)
gatne_kernel(const int* __restrict__ edge_index,    // [2, E]
             const float* __restrict__ edge_attr,   // [E, R]
             const int* __restrict__ nidx,          // [2, E, K]
             const float* __restrict__ emb,         // [N, D]
             const float* __restrict__ utab,        // [N, R, U]
             const float* __restrict__ Wt,          // [R, U, A]
             const float* __restrict__ wv,          // [R, A]
             const float* __restrict__ Mt,          // [R, U, D]
             float* __restrict__ out)               // [2, E, D]
{
    extern __shared__ float smem[];
    const int tid = threadIdx.x;

    // --- cooperative loads of the shared weight tables ---
    {
        float4* d = (float4*)(smem + SM_M);
        const float4* s = (const float4*)Mt;
        for (int i = tid; i < (R_ * U_ * D_) / 4; i += THREADS) d[i] = s[i];
    }
    for (int i = tid; i < R_ * U_ * A_; i += THREADS) {
        int r = i >> 9, rem = i & 511, uu = rem >> 4, a = rem & 15;
        smem[SM_W + r * 512 + a * 32 + uu] = Wt[i];
    }
    if (tid < R_ * A_) smem[SM_w + tid] = wv[tid];
    __syncthreads();

    const int warp = tid >> 5, lane = tid & 31;
    float* q_s  = smem + SM_WARP0 + warp * WARP_FLOATS;
    float* ur_s = q_s + UR_OFF;
    float* wr_s = q_s + WR_OFF;
    const float* W_s = smem + SM_W;
    const float* w_s = smem + SM_w;

    const int es_base = (blockIdx.x * WPB + warp) * ES_PER_WARP;
    const int rg = lane >> 3;          // r-group for the t/score phase
    const int cg = lane & 7;
    const int a0 = 2 * cg, a1 = a0 + 1;

    // ================= Phase 1: per edge-side attention -> q =================
    #pragma unroll
    for (int b = 0; b < ES_PER_WARP; ++b) {
        const int es = es_base + b;
        const int e = es & (E_ - 1);
        const float4 ea = ((const float4*)edge_attr)[e];

        // neighbor indices: one warp-wide load, distributed by shuffle
        const int* nb = nidx + es * K_;
        int my_n = (lane < K_) ? __ldg(nb + lane) : 0;

        // mean over K neighbors of u rows: lane holds flat (r*32+u) = 4*lane..4*lane+3
        float4 au = make_float4(0.f, 0.f, 0.f, 0.f);
        #pragma unroll
        for (int k = 0; k < K_; ++k) {
            int nbr = __shfl_sync(0xffffffffu, my_n, k);
            float4 t = ((const float4*)utab)[nbr * 32 + lane];
            au.x += t.x; au.y += t.y; au.z += t.z; au.w += t.w;
        }
        const float ik = 1.0f / (float)K_;
        au.x *= ik; au.y *= ik; au.z *= ik; au.w *= ik;

        // stash u_r to smem: layout [r*33 + u] (conflict-free)
        const int ub = 4 * cg;  // lane's flat index f = 4*lane+j -> r = lane>>3, u = 4*(lane&7)+j
        ur_s[rg * 33 + ub + 0] = au.x;
        ur_s[rg * 33 + ub + 1] = au.y;
        ur_s[rg * 33 + ub + 2] = au.z;
        ur_s[rg * 33 + ub + 3] = au.w;

        // W_r[u=lane][a] = sum_r ea[r] * W[r][u][a]  (W_s transposed [r][a][u])
        #pragma unroll
        for (int a = 0; a < A_; ++a) {
            float t = fmaf(ea.x, W_s[a * 32 + lane],
                      fmaf(ea.y, W_s[512 + a * 32 + lane],
                      fmaf(ea.z, W_s[1024 + a * 32 + lane],
                           ea.w * W_s[1536 + a * 32 + lane])));
            wr_s[lane * 17 + a] = t;
        }
        __syncwarp();

        // t[r=rg][a0], t[r=rg][a1] = sum_u u_r[r][u] * W_r[u][a]
        float t0 = 0.f, t1 = 0.f;
        #pragma unroll
        for (int uu = 0; uu < U_; ++uu) {
            float urv = ur_s[rg * 33 + uu];
            t0 = fmaf(urv, wr_s[uu * 17 + a0], t0);
            t1 = fmaf(urv, wr_s[uu * 17 + a1], t1);
        }
        // w_r[a] = ea . w[:, a]
        float wr0 = fmaf(ea.x, w_s[a0], fmaf(ea.y, w_s[16 + a0],
                    fmaf(ea.z, w_s[32 + a0], ea.w * w_s[48 + a0])));
        float wr1 = fmaf(ea.x, w_s[a1], fmaf(ea.y, w_s[16 + a1],
                    fmaf(ea.z, w_s[32 + a1], ea.w * w_s[48 + a1])));
        float sc = tanh_fast(t0) * wr0 + tanh_fast(t1) * wr1;

        // reduce scores within 8-lane r-group
        sc += __shfl_xor_sync(0xffffffffu, sc, 1);
        sc += __shfl_xor_sync(0xffffffffu, sc, 2);
        sc += __shfl_xor_sync(0xffffffffu, sc, 4);
        // softmax over the 4 r-groups
        float mx = sc;
        mx = fmaxf(mx, __shfl_xor_sync(0xffffffffu, mx, 8));
        mx = fmaxf(mx, __shfl_xor_sync(0xffffffffu, mx, 16));
        float ex = __expf(sc - mx);
        float ssum = ex;
        ssum += __shfl_xor_sync(0xffffffffu, ssum, 8);
        ssum += __shfl_xor_sync(0xffffffffu, ssum, 16);
        float att = __fdividef(ex, ssum);  // attention for r = rg
        float av0 = __shfl_sync(0xffffffffu, att, 0);
        float av1 = __shfl_sync(0xffffffffu, att, 8);
        float av2 = __shfl_sync(0xffffffffu, att, 16);
        float av3 = __shfl_sync(0xffffffffu, att, 24);

        // v[u=lane] = sum_r att[r] * u_r[r][lane]
        float vv = fmaf(av0, ur_s[0 * 33 + lane],
                   fmaf(av1, ur_s[1 * 33 + lane],
                   fmaf(av2, ur_s[2 * 33 + lane],
                        av3 * ur_s[3 * 33 + lane])));

        // q[b][r*32+u] = ea[r] * v[u]
        q_s[b * 128 +      lane] = ea.x * vv;
        q_s[b * 128 + 32 + lane] = ea.y * vv;
        q_s[b * 128 + 64 + lane] = ea.z * vv;
        q_s[b * 128 + 96 + lane] = ea.w * vv;
        __syncwarp();
    }

    // ================= Phase 2: out = b + q @ M, batched over 4 edge-sides ===
    float4 acc[4];
    #pragma unroll
    for (int b = 0; b < 4; ++b) {
        int ent = __ldg(edge_index + es_base + b);
        acc[b] = ((const float4*)emb)[ent * 32 + lane];   // b gather, coalesced
    }
    const float4* M4s = (const float4*)(smem + SM_M);
    const float4* q4  = (const float4*)q_s;
    #pragma unroll 2
    for (int ru4 = 0; ru4 < 32; ++ru4) {
        float4 qv0 = q4[ru4];
        float4 qv1 = q4[32 + ru4];
        float4 qv2 = q4[64 + ru4];
        float4 qv3 = q4[96 + ru4];
        MSTEP(0, x); MSTEP(1, y); MSTEP(2, z); MSTEP(3, w);
    }

    // ================= L2-normalize rows and store =================
    #pragma unroll
    for (int b = 0; b < 4; ++b) {
        float ss = acc[b].x * acc[b].x + acc[b].y * acc[b].y
                 + acc[b].z * acc[b].z + acc[b].w * acc[b].w;
        ss += __shfl_xor_sync(0xffffffffu, ss, 1);
        ss += __shfl_xor_sync(0xffffffffu, ss, 2);
        ss += __shfl_xor_sync(0xffffffffu, ss, 4);
        ss += __shfl_xor_sync(0xffffffffu, ss, 8);
        ss += __shfl_xor_sync(0xffffffffu, ss, 16);
        float norm = sqrtf(ss);
        float inv = 1.0f / fmaxf(norm, 1e-12f);
        float4 o = acc[b];
        o.x *= inv; o.y *= inv; o.z *= inv; o.w *= inv;
        ((float4*)out)[(es_base + b) * 32 + lane] = o;
    }
}

extern "C" void kernel_launch(void* const* d_in, const int* in_sizes, int n_in,
                              void* d_out, int out_size)
{
    (void)in_sizes; (void)n_in; (void)out_size;
    const int*   edge_index = (const int*)d_in[0];
    const float* edge_attr  = (const float*)d_in[1];
    const int*   nidx       = (const int*)d_in[2];
    const float* emb        = (const float*)d_in[3];
    const float* utab       = (const float*)d_in[4];
    const float* Wt         = (const float*)d_in[5];
    const float* wv         = (const float*)d_in[6];
    const float* Mt         = (const float*)d_in[7];
    float* out = (float*)d_out;

    cudaFuncSetAttribute(gatne_kernel,
                         cudaFuncAttributeMaxDynamicSharedMemorySize, SMEM_BYTES);
    gatne_kernel<<<NBLOCKS, THREADS, SMEM_BYTES>>>(
        edge_index, edge_attr, nidx, emb, utab, Wt, wv, Mt, out);
}

// round 4
// speedup vs baseline: 1.6628x; 1.0108x over previous
#include <cuda_runtime.h>
#include <math.h>

// Problem constants (GraphEmbedderGATNE): N=200000, R=4, D=128, U=32, A=16, E=131072, K=10
#define N_ENT 200000
#define R_ 4
#define D_ 128
#define U_ 32
#define A_ 16
#define E_ 131072
#define K_ 10
#define ES_TOTAL (2 * E_)                 // 262144 edge-sides
#define WPB 22                            // warps per block
#define ES_PER_WARP 8
#define THREADS (WPB * 32)                // 704
#define ES_PER_BLOCK (WPB * ES_PER_WARP)  // 176
#define NBLOCKS ((ES_TOTAL + ES_PER_BLOCK - 1) / ES_PER_BLOCK)  // 1490

// Shared-memory layout (float offsets)
#define SM_M 0                            // M: [(r*32+u)*128 + d], 16384 floats
#define SM_W (SM_M + R_ * U_ * D_)        // W transposed: [r*512 + a*32 + u], 2048 floats
#define SM_w (SM_W + R_ * U_ * A_)        // w: [r*16 + a], 64 floats
#define SM_WARP0 (SM_w + R_ * A_)         // 18496
// per-warp scratch:
#define Q_OFF 0                           // q: [b*128 + r*32 + u], 1024 floats (8 edge-sides)
#define UR_OFF 1024                       // ur: [r*33 + u] (conflict-free), 132 floats
#define WR_OFF (UR_OFF + 132)             // Wr: [u*18 + a] (float2-aligned, conflict-free), 576
#define WARP_FLOATS (WR_OFF + 576)        // 1732 floats / warp
#define SMEM_FLOATS (SM_WARP0 + WPB * WARP_FLOATS)   // 56600
#define SMEM_BYTES (SMEM_FLOATS * 4)      // 226400 bytes (<= 232448 max dynamic)

__device__ __forceinline__ float tanh_fast(float x) {
    float y;
    asm("tanh.approx.f32 %0, %1;" : "=f"(y) : "f"(x));
    return y;
}

// One mat-vec micro-step: consume component COMP of the 8 staged q-float4s
// against M row (ru4*4 + J); 32 FMAs (8 edge-sides x 4 d) per LDS.128 of M.
#define MSTEP8(J, COMP) do {                                                  \
    float4 mv = M4s[(ru4 * 4 + (J)) * 32 + lane];                             \
    _Pragma("unroll")                                                         \
    for (int bb = 0; bb < 8; ++bb) {                                          \
        acc[bb].x = fmaf(qv[bb].COMP, mv.x, acc[bb].x);                       \
        acc[bb].y = fmaf(qv[bb].COMP, mv.y, acc[bb].y);                       \
        acc[bb].z = fmaf(qv[bb].COMP, mv.z, acc[bb].z);                       \
        acc[bb].w = fmaf(qv[bb].COMP, mv.w, acc[bb].w);                       \
    }                                                                         \
} while (0)

__global__ void __launch_bounds__(THREADS, 1)
gatne_kernel(const int* __restrict__ edge_index,    // [2, E]
             const float* __restrict__ edge_attr,   // [E, R]
             const int* __restrict__ nidx,          // [2, E, K]
             const float* __restrict__ emb,         // [N, D]
             const float* __restrict__ utab,        // [N, R, U]
             const float* __restrict__ Wt,          // [R, U, A]
             const float* __restrict__ wv,          // [R, A]
             const float* __restrict__ Mt,          // [R, U, D]
             float* __restrict__ out)               // [2, E, D]
{
    extern __shared__ float smem[];
    const int tid = threadIdx.x;

    // --- cooperative loads of the shared weight tables ---
    {
        float4* d = (float4*)(smem + SM_M);
        const float4* s = (const float4*)Mt;
        for (int i = tid; i < (R_ * U_ * D_) / 4; i += THREADS) d[i] = s[i];
    }
    for (int i = tid; i < R_ * U_ * A_; i += THREADS) {
        int r = i >> 9, rem = i & 511, uu = rem >> 4, a = rem & 15;
        smem[SM_W + r * 512 + a * 32 + uu] = Wt[i];
    }
    if (tid < R_ * A_) smem[SM_w + tid] = wv[tid];
    __syncthreads();

    const int warp = tid >> 5, lane = tid & 31;
    float* q_s  = smem + SM_WARP0 + warp * WARP_FLOATS;
    float* ur_s = q_s + UR_OFF;
    float* wr_s = q_s + WR_OFF;
    const float* W_s = smem + SM_W;
    const float* w_s = smem + SM_w;

    const int es_base = (blockIdx.x * WPB + warp) * ES_PER_WARP;
    const int rg = lane >> 3;          // r-group for the t/score phase
    const int cg = lane & 7;
    const int a0 = 2 * cg;

    // ================= Phase 1: per edge-side attention -> q =================
    #pragma unroll 1
    for (int b = 0; b < ES_PER_WARP; ++b) {
        const int es = es_base + b;
        if (es < ES_TOTAL) {
            const int e = es & (E_ - 1);
            const float4 ea = ((const float4*)edge_attr)[e];

            // neighbor indices: one warp-wide load, distributed by shuffle
            const int* nb = nidx + es * K_;
            int my_n = (lane < K_) ? __ldg(nb + lane) : 0;

            // mean over K neighbors of u rows: lane holds flat (r*32+u) = 4*lane..4*lane+3
            float4 au = make_float4(0.f, 0.f, 0.f, 0.f);
            #pragma unroll
            for (int k = 0; k < K_; ++k) {
                int nbr = __shfl_sync(0xffffffffu, my_n, k);
                float4 t = ((const float4*)utab)[nbr * 32 + lane];
                au.x += t.x; au.y += t.y; au.z += t.z; au.w += t.w;
            }
            const float ik = 1.0f / (float)K_;
            au.x *= ik; au.y *= ik; au.z *= ik; au.w *= ik;

            // stash u_r to smem: layout [r*33 + u] (conflict-free)
            const int ub = 4 * cg;  // flat f = 4*lane+j -> r = lane>>3, u = 4*(lane&7)+j
            ur_s[rg * 33 + ub + 0] = au.x;
            ur_s[rg * 33 + ub + 1] = au.y;
            ur_s[rg * 33 + ub + 2] = au.z;
            ur_s[rg * 33 + ub + 3] = au.w;

            // W_r[u=lane][a] = sum_r ea[r] * W[r][u][a]  (W_s transposed [r][a][u])
            // packed as float2 pairs into wr_s [u*18 + a]
            #pragma unroll
            for (int a2 = 0; a2 < 8; ++a2) {
                int a = 2 * a2;
                float f0 = fmaf(ea.x, W_s[a * 32 + lane],
                           fmaf(ea.y, W_s[512 + a * 32 + lane],
                           fmaf(ea.z, W_s[1024 + a * 32 + lane],
                                ea.w * W_s[1536 + a * 32 + lane])));
                float f1 = fmaf(ea.x, W_s[(a + 1) * 32 + lane],
                           fmaf(ea.y, W_s[512 + (a + 1) * 32 + lane],
                           fmaf(ea.z, W_s[1024 + (a + 1) * 32 + lane],
                                ea.w * W_s[1536 + (a + 1) * 32 + lane])));
                ((float2*)(wr_s + lane * 18))[a2] = make_float2(f0, f1);
            }
            __syncwarp();

            // t[r=rg][a0], t[r=rg][a0+1] = sum_u u_r[r][u] * W_r[u][a]
            float t0 = 0.f, t1 = 0.f;
            #pragma unroll
            for (int uu = 0; uu < U_; ++uu) {
                float urv = ur_s[rg * 33 + uu];
                float2 w2 = *(const float2*)(wr_s + uu * 18 + a0);
                t0 = fmaf(urv, w2.x, t0);
                t1 = fmaf(urv, w2.y, t1);
            }
            // w_r[a] = ea . w[:, a]
            float wr0 = fmaf(ea.x, w_s[a0], fmaf(ea.y, w_s[16 + a0],
                        fmaf(ea.z, w_s[32 + a0], ea.w * w_s[48 + a0])));
            float wr1 = fmaf(ea.x, w_s[a0 + 1], fmaf(ea.y, w_s[16 + a0 + 1],
                        fmaf(ea.z, w_s[32 + a0 + 1], ea.w * w_s[48 + a0 + 1])));
            float sc = tanh_fast(t0) * wr0 + tanh_fast(t1) * wr1;

            // reduce scores within 8-lane r-group
            sc += __shfl_xor_sync(0xffffffffu, sc, 1);
            sc += __shfl_xor_sync(0xffffffffu, sc, 2);
            sc += __shfl_xor_sync(0xffffffffu, sc, 4);
            // softmax over the 4 r-groups
            float mx = sc;
            mx = fmaxf(mx, __shfl_xor_sync(0xffffffffu, mx, 8));
            mx = fmaxf(mx, __shfl_xor_sync(0xffffffffu, mx, 16));
            float ex = __expf(sc - mx);
            float ssum = ex;
            ssum += __shfl_xor_sync(0xffffffffu, ssum, 8);
            ssum += __shfl_xor_sync(0xffffffffu, ssum, 16);
            float att = __fdividef(ex, ssum);  // attention for r = rg
            float av0 = __shfl_sync(0xffffffffu, att, 0);
            float av1 = __shfl_sync(0xffffffffu, att, 8);
            float av2 = __shfl_sync(0xffffffffu, att, 16);
            float av3 = __shfl_sync(0xffffffffu, att, 24);

            // v[u=lane] = sum_r att[r] * u_r[r][lane]
            float vv = fmaf(av0, ur_s[0 * 33 + lane],
                       fmaf(av1, ur_s[1 * 33 + lane],
                       fmaf(av2, ur_s[2 * 33 + lane],
                            av3 * ur_s[3 * 33 + lane])));

            // q[b][r*32+u] = ea[r] * v[u]
            q_s[b * 128 +      lane] = ea.x * vv;
            q_s[b * 128 + 32 + lane] = ea.y * vv;
            q_s[b * 128 + 64 + lane] = ea.z * vv;
            q_s[b * 128 + 96 + lane] = ea.w * vv;
            __syncwarp();
        }
    }

    // ================= Phase 2: out = b + q @ M, batched over 8 edge-sides ===
    float4 acc[8];
    #pragma unroll
    for (int b = 0; b < 8; ++b) {
        int es = es_base + b;
        int ent = (es < ES_TOTAL) ? __ldg(edge_index + es) : 0;
        acc[b] = ((const float4*)emb)[ent * 32 + lane];   // b gather, coalesced
    }
    const float4* M4s = (const float4*)(smem + SM_M);
    const float4* q4  = (const float4*)q_s;
    #pragma unroll 1
    for (int ru4 = 0; ru4 < 32; ++ru4) {
        float4 qv[8];
        #pragma unroll
        for (int bb = 0; bb < 8; ++bb) qv[bb] = q4[bb * 32 + ru4];
        MSTEP8(0, x); MSTEP8(1, y); MSTEP8(2, z); MSTEP8(3, w);
    }

    // ================= L2-normalize rows and store =================
    #pragma unroll
    for (int b = 0; b < 8; ++b) {
        int es = es_base + b;
        float ss = acc[b].x * acc[b].x + acc[b].y * acc[b].y
                 + acc[b].z * acc[b].z + acc[b].w * acc[b].w;
        ss += __shfl_xor_sync(0xffffffffu, ss, 1);
        ss += __shfl_xor_sync(0xffffffffu, ss, 2);
        ss += __shfl_xor_sync(0xffffffffu, ss, 4);
        ss += __shfl_xor_sync(0xffffffffu, ss, 8);
        ss += __shfl_xor_sync(0xffffffffu, ss, 16);
        float norm = sqrtf(ss);
        float inv = 1.0f / fmaxf(norm, 1e-12f);
        float4 o = acc[b];
        o.x *= inv; o.y *= inv; o.z *= inv; o.w *= inv;
        if (es < ES_TOTAL)
            ((float4*)out)[es * 32 + lane] = o;
    }
}

extern "C" void kernel_launch(void* const* d_in, const int* in_sizes, int n_in,
                              void* d_out, int out_size)
{
    (void)in_sizes; (void)n_in; (void)out_size;
    const int*   edge_index = (const int*)d_in[0];
    const float* edge_attr  = (const float*)d_in[1];
    const int*   nidx       = (const int*)d_in[2];
    const float* emb        = (const float*)d_in[3];
    const float* utab       = (const float*)d_in[4];
    const float* Wt         = (const float*)d_in[5];
    const float* wv         = (const float*)d_in[6];
    const float* Mt         = (const float*)d_in[7];
    float* out = (float*)d_out;

    cudaFuncSetAttribute(gatne_kernel,
                         cudaFuncAttributeMaxDynamicSharedMemorySize, SMEM_BYTES);
    gatne_kernel<<<NBLOCKS, THREADS, SMEM_BYTES>>>(
        edge_index, edge_attr, nidx, emb, utab, Wt, wv, Mt, out);
}